// round 12
// baseline (speedup 1.0000x reference)
#include <cuda_runtime.h>
#include <cuda_bf16.h>

// Problem constants
#define B_SZ   512
#define IN_F   512
#define OUT_F  64
#define KD     16
#define NF     (OUT_F * KD)   // 1024
#define KS     4              // k-splits in GEMM

typedef unsigned long long u64;
typedef unsigned int u32;

// Scratch: 4 bf16 partial M buffers [o][b][k-pairs]; S accum [o][j]; counters
__device__ u32 g_Mpb[KS][OUT_F * B_SZ * KD / 2];   // bf16x2
__device__ float g_S[OUT_F * B_SZ];
__device__ unsigned int g_cnt[OUT_F * 4];          // zero-init, self-resetting

// ---- packed helpers (sm_103a) ---------------------------------------------
__device__ __forceinline__ u64 ffma2(u64 a, u64 b, u64 c) {
    u64 r; asm("fma.rn.f32x2 %0, %1, %2, %3;" : "=l"(r) : "l"(a), "l"(b), "l"(c)); return r;
}
__device__ __forceinline__ u32 hadd2b(u32 a, u32 b) {
    u32 r; asm("add.rn.bf16x2 %0, %1, %2;" : "=r"(r) : "r"(a), "r"(b)); return r;
}
__device__ __forceinline__ u32 habs2(u32 a) { return a & 0x7FFF7FFFu; }
__device__ __forceinline__ u32 cvt2(float lo, float hi) {
    u32 r; asm("cvt.rn.bf16x2.f32 %0, %1, %2;" : "=r"(r) : "f"(hi), "f"(lo)); return r;
}
__device__ __forceinline__ void unpack2(u64 v, float& lo, float& hi) {
    asm("mov.b64 {%0, %1}, %2;" : "=f"(lo), "=f"(hi) : "l"(v));
}
// 4-way bf16x2 sum, FIXED op order (identical wherever M rows are rebuilt)
__device__ __forceinline__ uint4 sum4(uint4 a, uint4 b, uint4 c, uint4 d) {
    uint4 r;
    r.x = hadd2b(hadd2b(a.x, b.x), hadd2b(c.x, d.x));
    r.y = hadd2b(hadd2b(a.y, b.y), hadd2b(c.y, d.y));
    r.z = hadd2b(hadd2b(a.z, b.z), hadd2b(c.z, d.z));
    r.w = hadd2b(hadd2b(a.w, b.w), hadd2b(c.w, d.w));
    return r;
}

// ---------------------------------------------------------------------------
// Kernel A: k-split GEMM (UNCHANGED from R11).
// ---------------------------------------------------------------------------
#define TM 64
#define TN 64
#define TK 32
#define KC (IN_F / KS)        // 128
#define NSTEP (KC / TK)       // 4

__global__ __launch_bounds__(256) void mbd_gemm_kernel(
    const float* __restrict__ x, const float* __restrict__ T)
{
    __shared__ float2 xsd[2][TM][TK + 1];
    __shared__ float  Ts[2][TK][TN];

    const int tid = threadIdx.x;
    const int nt  = blockIdx.x;
    const int mt  = blockIdx.y;
    const int ks  = blockIdx.z;

    if (ks == 0) {
        int id = mt * 16 + nt;
        g_S[id * 256 + tid] = 0.0f;
    }

    const int tx = tid & 15;
    const int ty = tid >> 4;
    const int m0 = mt * TM;
    const int n0 = nt * TN;
    const int kb = ks * KC;
    const int r = ty * 4;
    const int c = tx * 4;

    const int lm = (tid * 4) >> 5, lk = (tid * 4) & 31;
    const int bk = (tid * 4) >> 6, bn = (tid * 4) & 63;
    const float* xp0 = &x[(m0 + lm) * IN_F + kb + lk];
    const float* xp1 = xp0 + 32 * IN_F;
    const float* Tp0 = &T[(kb + bk) * NF + n0 + bn];
    const float* Tp1 = Tp0 + 16 * NF;

    u64 acc[4][2];
#pragma unroll
    for (int i = 0; i < 4; i++) { acc[i][0] = 0ULL; acc[i][1] = 0ULL; }

    {
        float4 a0 = *(const float4*)xp0;
        float4 a1 = *(const float4*)xp1;
        float4 b0 = *(const float4*)Tp0;
        float4 b1 = *(const float4*)Tp1;
        xsd[0][lm][lk + 0] = make_float2(a0.x, a0.x);
        xsd[0][lm][lk + 1] = make_float2(a0.y, a0.y);
        xsd[0][lm][lk + 2] = make_float2(a0.z, a0.z);
        xsd[0][lm][lk + 3] = make_float2(a0.w, a0.w);
        xsd[0][lm + 32][lk + 0] = make_float2(a1.x, a1.x);
        xsd[0][lm + 32][lk + 1] = make_float2(a1.y, a1.y);
        xsd[0][lm + 32][lk + 2] = make_float2(a1.z, a1.z);
        xsd[0][lm + 32][lk + 3] = make_float2(a1.w, a1.w);
        *(float4*)&Ts[0][bk][bn] = b0;
        *(float4*)&Ts[0][bk + 16][bn] = b1;
    }

    int buf = 0;
#pragma unroll
    for (int s = 0; s < NSTEP; s++) {
        __syncthreads();

        float4 na0, na1, nb0, nb1;
        if (s < NSTEP - 1) {
            na0 = *(const float4*)(xp0 + (s + 1) * TK);
            na1 = *(const float4*)(xp1 + (s + 1) * TK);
            nb0 = *(const float4*)(Tp0 + (s + 1) * TK * NF);
            nb1 = *(const float4*)(Tp1 + (s + 1) * TK * NF);
        }

#pragma unroll
        for (int kk = 0; kk < TK; kk++) {
            u64 a0 = *(const u64*)&xsd[buf][r + 0][kk];
            u64 a1 = *(const u64*)&xsd[buf][r + 1][kk];
            u64 a2 = *(const u64*)&xsd[buf][r + 2][kk];
            u64 a3 = *(const u64*)&xsd[buf][r + 3][kk];
            ulonglong2 bb = *(const ulonglong2*)&Ts[buf][kk][c];
            acc[0][0] = ffma2(a0, bb.x, acc[0][0]); acc[0][1] = ffma2(a0, bb.y, acc[0][1]);
            acc[1][0] = ffma2(a1, bb.x, acc[1][0]); acc[1][1] = ffma2(a1, bb.y, acc[1][1]);
            acc[2][0] = ffma2(a2, bb.x, acc[2][0]); acc[2][1] = ffma2(a2, bb.y, acc[2][1]);
            acc[3][0] = ffma2(a3, bb.x, acc[3][0]); acc[3][1] = ffma2(a3, bb.y, acc[3][1]);
        }

        if (s < NSTEP - 1) {
            int b2 = buf ^ 1;
            xsd[b2][lm][lk + 0] = make_float2(na0.x, na0.x);
            xsd[b2][lm][lk + 1] = make_float2(na0.y, na0.y);
            xsd[b2][lm][lk + 2] = make_float2(na0.z, na0.z);
            xsd[b2][lm][lk + 3] = make_float2(na0.w, na0.w);
            xsd[b2][lm + 32][lk + 0] = make_float2(na1.x, na1.x);
            xsd[b2][lm + 32][lk + 1] = make_float2(na1.y, na1.y);
            xsd[b2][lm + 32][lk + 2] = make_float2(na1.z, na1.z);
            xsd[b2][lm + 32][lk + 3] = make_float2(na1.w, na1.w);
            *(float4*)&Ts[b2][bk][bn] = nb0;
            *(float4*)&Ts[b2][bk + 16][bn] = nb1;
        }
        buf ^= 1;
    }

    const int of = n0 + c;
    const int o  = of >> 4;
    const int k  = of & 15;
    u32* dst = g_Mpb[ks];
#pragma unroll
    for (int ii = 0; ii < 4; ii++) {
        int b = m0 + r + ii;
        float c0, c1, c2, c3;
        unpack2(acc[ii][0], c0, c1);
        unpack2(acc[ii][1], c2, c3);
        uint2 v; v.x = cvt2(c0, c1); v.y = cvt2(c2, c3);
        *(uint2*)&dst[(o * B_SZ + b) * (KD / 2) + k / 2] = v;
    }
}

// ---------------------------------------------------------------------------
// Kernel B: symmetric pairwise. Per o: 4 diagonal + 6 off-diagonal chunk
// tiles (grid (64, 10), 128 threads). Off-diagonal tiles compute each
// unordered pair once and scatter the term to BOTH S[j] and S[i] (staggered
// i-walk -> per-warp conflict-free scatter arrays, no atomics).
// ---------------------------------------------------------------------------
__device__ __forceinline__ float bterm(const uint4* __restrict__ s4,
                                       const u32* __restrict__ mjn, int i)
{
    uint4 va = s4[i * 2 + 0];
    uint4 vb = s4[i * 2 + 1];
    u32 d0 = habs2(hadd2b(va.x, mjn[0]));
    u32 d1 = habs2(hadd2b(va.y, mjn[1]));
    u32 d2 = habs2(hadd2b(va.z, mjn[2]));
    u32 d3 = habs2(hadd2b(va.w, mjn[3]));
    u32 d4 = habs2(hadd2b(vb.x, mjn[4]));
    u32 d5 = habs2(hadd2b(vb.y, mjn[5]));
    u32 d6 = habs2(hadd2b(vb.z, mjn[6]));
    u32 d7 = habs2(hadd2b(vb.w, mjn[7]));
    u32 t = hadd2b(hadd2b(hadd2b(d0, d1), hadd2b(d2, d3)),
                   hadd2b(hadd2b(d4, d5), hadd2b(d6, d7)));
    float lo = __uint_as_float(t << 16);
    float hi = __uint_as_float(t & 0xFFFF0000u);
    return __expf(-(lo + hi));
}

__device__ __forceinline__ void stage_chunk(u32* dst, int o, int chunk, int tid)
{
    const int off4 = (o * B_SZ + chunk * 128) * 2;     // uint4 units
#pragma unroll
    for (int t = 0; t < 2; t++) {
        int e = tid + t * 128;
        uint4 a = ((const uint4*)g_Mpb[0])[off4 + e];
        uint4 b = ((const uint4*)g_Mpb[1])[off4 + e];
        uint4 c = ((const uint4*)g_Mpb[2])[off4 + e];
        uint4 d = ((const uint4*)g_Mpb[3])[off4 + e];
        ((uint4*)dst)[e] = sum4(a, b, c, d);
    }
}

__device__ __constant__ signed char PAIR_A[10] = {0,1,2,3, 0,0,0,1,1,2};
__device__ __constant__ signed char PAIR_B[10] = {0,1,2,3, 1,2,3,2,3,3};

__global__ __launch_bounds__(128) void mbd_pairwise_kernel(
    const float* __restrict__ w, float* __restrict__ out)
{
    __shared__ u32 sJb[128 * 8];               // chunk-a bf16x2 rows, 4 KB
    __shared__ u32 sIb[128 * 8];               // chunk-b rows, 4 KB
    __shared__ float sS[4][128];               // per-warp scatter arrays, 2 KB
    __shared__ int lastA, lastB;

    const int o   = blockIdx.x;
    const int p   = blockIdx.y;                // tile-pair 0..9
    const int ca  = PAIR_A[p];
    const int cb  = PAIR_B[p];
    const bool diag = (ca == cb);
    const int tid = threadIdx.x;
    const int wid = tid >> 5;

    stage_chunk(sJb, o, ca, tid);
    if (!diag) {
        stage_chunk(sIb, o, cb, tid);
        sS[0][tid] = 0.f; sS[1][tid] = 0.f; sS[2][tid] = 0.f; sS[3][tid] = 0.f;
    }
    __syncthreads();

    // Negated bf16x2 row j = ca*128+tid (sign flip exact)
    u32 mjn[8];
#pragma unroll
    for (int pp = 0; pp < 8; pp++)
        mjn[pp] = sJb[tid * 8 + pp] ^ 0x80008000u;

    if (diag) {
        // Broadcast walk, 4 independent accumulators (proven R10/R11 loop)
        const uint4* s4 = (const uint4*)sJb;
        float S0 = 0.f, S1 = 0.f, S2 = 0.f, S3 = 0.f;
#pragma unroll 2
        for (int i = 0; i < 128; i += 4) {
            S0 += bterm(s4, mjn, i + 0);
            S1 += bterm(s4, mjn, i + 1);
            S2 += bterm(s4, mjn, i + 2);
            S3 += bterm(s4, mjn, i + 3);
        }
        float S = (S0 + S1) + (S2 + S3);
        atomicAdd(&g_S[o * B_SZ + ca * 128 + tid], S);
    } else {
        // Staggered walk: step s -> i = (tid+s)&127 (lanes always distinct)
        const uint4* s4 = (const uint4*)sIb;
        float* mS = sS[wid];
        float Sj = 0.f;
#pragma unroll 2
        for (int s = 0; s < 128; s++) {
            int i = (tid + s) & 127;
            float term = bterm(s4, mjn, i);
            Sj += term;
            mS[i] += term;                     // conflict-free, race-free
        }
        __syncthreads();
        float Si = (sS[0][tid] + sS[1][tid]) + (sS[2][tid] + sS[3][tid]);
        atomicAdd(&g_S[o * B_SZ + ca * 128 + tid], Sj);
        atomicAdd(&g_S[o * B_SZ + cb * 128 + tid], Si);
    }

    // Finalize: each chunk has exactly 4 contributing blocks
    __threadfence();
    __syncthreads();
    if (tid == 0) {
        lastA = (atomicAdd(&g_cnt[o * 4 + ca], 1u) == 3u);
        lastB = diag ? 0 : (atomicAdd(&g_cnt[o * 4 + cb], 1u) == 3u);
    }
    __syncthreads();
    if (lastA) {
        __threadfence();
        int j = ca * 128 + tid;
        out[j * OUT_F + o] = w[j] * (g_S[o * B_SZ + j] - 1.0f);
        if (tid == 0) g_cnt[o * 4 + ca] = 0u;
    }
    if (lastB) {
        __threadfence();
        int j = cb * 128 + tid;
        out[j * OUT_F + o] = w[j] * (g_S[o * B_SZ + j] - 1.0f);
        if (tid == 0) g_cnt[o * 4 + cb] = 0u;
    }
}

// ---------------------------------------------------------------------------
extern "C" void kernel_launch(void* const* d_in, const int* in_sizes, int n_in,
                              void* d_out, int out_size)
{
    const float* x = (const float*)d_in[0];   // [512, 512]
    const float* w = (const float*)d_in[1];   // [1, 512]
    const float* T = (const float*)d_in[2];   // [512, 64, 16]
    float* out = (float*)d_out;               // [512, 64]

    (void)in_sizes; (void)n_in; (void)out_size;

    mbd_gemm_kernel<<<dim3(NF / TN, B_SZ / TM, KS), 256>>>(x, T);
    mbd_pairwise_kernel<<<dim3(OUT_F, 10), 128>>>(w, out);
}

// round 13
// speedup vs baseline: 1.3193x; 1.3193x over previous
#include <cuda_runtime.h>
#include <cuda_bf16.h>

// Problem constants
#define B_SZ   512
#define IN_F   512
#define OUT_F  64
#define KD     16
#define NF     (OUT_F * KD)   // 1024

typedef unsigned long long u64;
typedef unsigned int u32;

// Scratch: bf16 inputs (x row-major, T transposed), bf16 M [o][b][k/2], S, counters
__device__ u32 g_xb[B_SZ * IN_F / 2];          // x as bf16x2, [m][k]
__device__ u32 g_Tb[NF * IN_F / 2];            // T^T as bf16x2, [n][k]
__device__ u32 g_Mb[OUT_F * B_SZ * KD / 2];    // M as bf16x2, [o][b][k/2]
__device__ float g_S[OUT_F * B_SZ];
__device__ unsigned int g_cnt[OUT_F * 4];      // zero-init, self-resetting

// ---- packed helpers (sm_103a) ---------------------------------------------
__device__ __forceinline__ u32 hadd2b(u32 a, u32 b) {
    u32 r; asm("add.rn.bf16x2 %0, %1, %2;" : "=r"(r) : "r"(a), "r"(b)); return r;
}
__device__ __forceinline__ u32 habs2(u32 a) { return a & 0x7FFF7FFFu; }
// pack two f32 into bf16x2: lo -> low half, hi -> high half
__device__ __forceinline__ u32 cvt2(float lo, float hi) {
    u32 r; asm("cvt.rn.bf16x2.f32 %0, %1, %2;" : "=r"(r) : "f"(hi), "f"(lo)); return r;
}
__device__ __forceinline__ void mma_bf16(float& d0, float& d1, float& d2, float& d3,
                                         u32 a0, u32 a1, u32 a2, u32 a3,
                                         u32 b0, u32 b1) {
    asm volatile(
        "mma.sync.aligned.m16n8k16.row.col.f32.bf16.bf16.f32 "
        "{%0,%1,%2,%3}, {%4,%5,%6,%7}, {%8,%9}, {%0,%1,%2,%3};"
        : "+f"(d0), "+f"(d1), "+f"(d2), "+f"(d3)
        : "r"(a0), "r"(a1), "r"(a2), "r"(a3), "r"(b0), "r"(b1));
}

// ---------------------------------------------------------------------------
// Kernel P: prep. Grid 128 x 256 threads.
//  - converts x -> g_xb (bf16x2)
//  - transposes+converts T -> g_Tb[n][k] (bf16x2) via smem tiles
//  - zeroes g_S
// Block (bx, by): T tile k0=by*64, n0=bx*64  (grid 16 x 8)
// ---------------------------------------------------------------------------
__global__ __launch_bounds__(256) void mbd_prep_kernel(
    const float* __restrict__ x, const float* __restrict__ T)
{
    __shared__ float sT[64][68];               // padded (272B rows, 16B-aligned)

    const int tid = threadIdx.x;
    const int bx  = blockIdx.x;                // 0..15  (n tile)
    const int by  = blockIdx.y;                // 0..7   (k tile)
    const int bid = by * 16 + bx;              // 0..127
    const int k0  = by * 64;
    const int n0  = bx * 64;

    // x conversion: 131072 u32 total -> 1024 per block -> 4 per thread
    {
        const float2* xs = (const float2*)x;
#pragma unroll
        for (int i = 0; i < 4; i++) {
            int e = bid * 1024 + tid * 4 + i;
            float2 f = xs[e];
            g_xb[e] = cvt2(f.x, f.y);
        }
    }
    // g_S zeroing: 32768 floats -> 256 per block -> 1 per thread
    g_S[bid * 256 + tid] = 0.0f;

    // Load T tile (64 k-rows x 64 n-cols) coalesced
    {
        int r  = tid >> 2;                     // 0..63  (k row)
        int c4 = (tid & 3) * 4;                // float4 col base
#pragma unroll
        for (int i = 0; i < 4; i++) {
            float4 v = ((const float4*)T)[(k0 + r) * (NF / 4) + (n0 / 4) + c4 + i];
            *(float4*)&sT[r][(c4 + i) * 4] = v;
        }
    }
    __syncthreads();

    // Write transposed bf16x2: g_Tb[n][k/2]
    {
        int nn   = tid >> 2;                   // 0..63
        int kblk = tid & 3;                    // 8 u32 each
#pragma unroll
        for (int i = 0; i < 8; i++) {
            int kk = kblk * 16 + i * 2;        // local k (even)
            u32 v = cvt2(sT[kk][nn], sT[kk + 1][nn]);
            g_Tb[(n0 + nn) * (IN_F / 2) + (k0 + kk) / 2] = v;
        }
    }
}

// ---------------------------------------------------------------------------
// Kernel A: bf16 tensor-core GEMM.  Grid (16 n-tiles, 8 m-tiles), 128 thr.
// Tile 64x64, K-chunk 64 (8 steps, double-buffered smem).
// Warp w computes rows 16w..16w+15 x all 64 cols via m16n8k16 HMMA.
// Epilogue: fp32 frags -> bf16x2 -> g_Mb[o][b][k/2].
// ---------------------------------------------------------------------------
#define GSTEP 8
// padded row: 64 bf16 = 128 B -> 144 B  (16B-aligned, frag loads conflict-free)
#define RB 144

__global__ __launch_bounds__(128) void mbd_gemm_kernel(void)
{
    __shared__ unsigned char Asb[2][64 * RB];  // 18.4 KB
    __shared__ unsigned char Bsb[2][64 * RB];  // 18.4 KB

    const int tid = threadIdx.x;
    const int w   = tid >> 5;                  // warp 0..3
    const int l   = tid & 31;
    const int g   = l >> 2;                    // 0..7
    const int tg  = l & 3;                     // 0..3
    const int nt  = blockIdx.x;                // n tile
    const int mt  = blockIdx.y;                // m tile
    const int m0  = mt * 64;
    const int n0  = nt * 64;

    // Staging coords: 512 uint4 per tile, 4 per thread (one row-half each)
    const int sr = tid >> 1;                   // row 0..63
    const int sc = (tid & 1) * 4;              // uint4 col base 0 or 4
    const uint4* xs4 = (const uint4*)g_xb;     // row = 64 uint4 (512 bf16)
    const uint4* Ts4 = (const uint4*)g_Tb;

    float d[8][4];
#pragma unroll
    for (int nc = 0; nc < 8; nc++)
#pragma unroll
        for (int i = 0; i < 4; i++) d[nc][i] = 0.f;

    // Prologue: stage step 0
#pragma unroll
    for (int i = 0; i < 4; i++) {
        uint4 va = xs4[(m0 + sr) * 64 + (sc + i)];
        uint4 vb = Ts4[(n0 + sr) * 64 + (sc + i)];
        *(uint4*)(Asb[0] + sr * RB + (sc + i) * 16) = va;
        *(uint4*)(Bsb[0] + sr * RB + (sc + i) * 16) = vb;
    }

    // Per-lane fragment byte offsets
    const int aoff = (w * 16 + g) * RB + tg * 4;

    int buf = 0;
#pragma unroll
    for (int s = 0; s < GSTEP; s++) {
        __syncthreads();

        uint4 pa[4], pb[4];
        if (s < GSTEP - 1) {
#pragma unroll
            for (int i = 0; i < 4; i++) {
                pa[i] = xs4[(m0 + sr) * 64 + (s + 1) * 8 + (sc + i)];
                pb[i] = Ts4[(n0 + sr) * 64 + (s + 1) * 8 + (sc + i)];
            }
        }

        const unsigned char* A = Asb[buf];
        const unsigned char* B = Bsb[buf];
#pragma unroll
        for (int kc = 0; kc < 4; kc++) {
            u32 a0 = *(const u32*)(A + aoff + kc * 32);
            u32 a1 = *(const u32*)(A + aoff + kc * 32 + 8 * RB);
            u32 a2 = *(const u32*)(A + aoff + kc * 32 + 16);
            u32 a3 = *(const u32*)(A + aoff + kc * 32 + 8 * RB + 16);
#pragma unroll
            for (int nc = 0; nc < 8; nc++) {
                const unsigned char* bp = B + (nc * 8 + g) * RB + tg * 4 + kc * 32;
                u32 b0 = *(const u32*)bp;
                u32 b1 = *(const u32*)(bp + 16);
                mma_bf16(d[nc][0], d[nc][1], d[nc][2], d[nc][3],
                         a0, a1, a2, a3, b0, b1);
            }
        }

        if (s < GSTEP - 1) {
            int b2 = buf ^ 1;
#pragma unroll
            for (int i = 0; i < 4; i++) {
                *(uint4*)(Asb[b2] + sr * RB + (sc + i) * 16) = pa[i];
                *(uint4*)(Bsb[b2] + sr * RB + (sc + i) * 16) = pb[i];
            }
        }
        buf ^= 1;
    }

    // Epilogue: frag (rows m0+16w+g, m0+16w+g+8; cols n0+nc*8+tg*2,+1)
    const int row0 = m0 + w * 16 + g;
#pragma unroll
    for (int nc = 0; nc < 8; nc++) {
        int col = n0 + nc * 8 + tg * 2;
        int o = col >> 4;
        int k = col & 15;                      // even
        g_Mb[(o * B_SZ + row0) * (KD / 2) + (k >> 1)]       = cvt2(d[nc][0], d[nc][1]);
        g_Mb[(o * B_SZ + row0 + 8) * (KD / 2) + (k >> 1)]   = cvt2(d[nc][2], d[nc][3]);
    }
}

// ---------------------------------------------------------------------------
// Kernel B: pairwise tiles + fused finalize (R11 structure, copy staging).
// grid (64 o, 4 j-chunk, 4 i-quarter), 128 threads; thread = one j, 128 i's.
// ---------------------------------------------------------------------------
__device__ __forceinline__ float bterm(const uint4* __restrict__ s4,
                                       const u32* __restrict__ mjn, int i)
{
    uint4 va = s4[i * 2 + 0];                  // ks 0..7  (bf16x2 x4)
    uint4 vb = s4[i * 2 + 1];                  // ks 8..15
    u32 d0 = habs2(hadd2b(va.x, mjn[0]));
    u32 d1 = habs2(hadd2b(va.y, mjn[1]));
    u32 d2 = habs2(hadd2b(va.z, mjn[2]));
    u32 d3 = habs2(hadd2b(va.w, mjn[3]));
    u32 d4 = habs2(hadd2b(vb.x, mjn[4]));
    u32 d5 = habs2(hadd2b(vb.y, mjn[5]));
    u32 d6 = habs2(hadd2b(vb.z, mjn[6]));
    u32 d7 = habs2(hadd2b(vb.w, mjn[7]));
    u32 t = hadd2b(hadd2b(hadd2b(d0, d1), hadd2b(d2, d3)),
                   hadd2b(hadd2b(d4, d5), hadd2b(d6, d7)));
    float lo = __uint_as_float(t << 16);       // bf16 -> f32 reinterpret
    float hi = __uint_as_float(t & 0xFFFF0000u);
    return __expf(-(lo + hi));
}

__global__ __launch_bounds__(128) void mbd_pairwise_kernel(
    const float* __restrict__ w, float* __restrict__ out)
{
    __shared__ u32 sJb[128 * 8];               // 4 KB
    __shared__ u32 sIb[128 * 8];               // 4 KB
    __shared__ int last;

    const int o   = blockIdx.x;
    const int jc  = blockIdx.y;                // j-chunk (128 j's)
    const int q   = blockIdx.z;                // i-quarter (128 i's)
    const int tid = threadIdx.x;
    const int j   = jc * 128 + tid;

    // Stage: straight copy from g_Mb (single buffer)
    {
        const int offJ4 = (o * B_SZ + jc * 128) * 2;   // uint4 units
        const int offI4 = (o * B_SZ + q  * 128) * 2;
#pragma unroll
        for (int t = 0; t < 2; t++) {
            int e = tid + t * 128;
            ((uint4*)sJb)[e] = ((const uint4*)g_Mb)[offJ4 + e];
            ((uint4*)sIb)[e] = ((const uint4*)g_Mb)[offI4 + e];
        }
    }
    __syncthreads();

    // Negated bf16x2 row j (sign flip exact)
    u32 mjn[8];
#pragma unroll
    for (int p = 0; p < 8; p++)
        mjn[p] = sJb[tid * 8 + p] ^ 0x80008000u;

    const uint4* s4 = (const uint4*)sIb;

    float S0 = 0.f, S1 = 0.f, S2 = 0.f, S3 = 0.f;
#pragma unroll 2
    for (int i = 0; i < 128; i += 4) {
        S0 += bterm(s4, mjn, i + 0);
        S1 += bterm(s4, mjn, i + 1);
        S2 += bterm(s4, mjn, i + 2);
        S3 += bterm(s4, mjn, i + 3);
    }
    float S = (S0 + S1) + (S2 + S3);

    atomicAdd(&g_S[o * B_SZ + j], S);          // coalesced REDG

    // Last block of the (o, jc) group applies the finalize
    __threadfence();
    __syncthreads();
    if (tid == 0)
        last = (atomicAdd(&g_cnt[o * 4 + jc], 1u) == 3u);
    __syncthreads();
    if (last) {
        __threadfence();                       // acquire: see peers' REDG
        float s = g_S[o * B_SZ + j];           // coalesced
        out[j * OUT_F + o] = w[j] * (s - 1.0f);
        if (tid == 0) g_cnt[o * 4 + jc] = 0u;  // reset for next graph replay
    }
}

// ---------------------------------------------------------------------------
extern "C" void kernel_launch(void* const* d_in, const int* in_sizes, int n_in,
                              void* d_out, int out_size)
{
    const float* x = (const float*)d_in[0];   // [512, 512]
    const float* w = (const float*)d_in[1];   // [1, 512]
    const float* T = (const float*)d_in[2];   // [512, 64, 16]
    float* out = (float*)d_out;               // [512, 64]

    (void)in_sizes; (void)n_in; (void)out_size;

    mbd_prep_kernel<<<dim3(16, 8), 256>>>(x, T);
    mbd_gemm_kernel<<<dim3(16, 8), 128>>>();
    mbd_pairwise_kernel<<<dim3(OUT_F, 4, 4), 128>>>(w, out);
}